// round 1
// baseline (speedup 1.0000x reference)
#include <cuda_runtime.h>

// Segmented GroupNorm: N rows x C=64 channels, G=32 groups (Cg=2),
// segments (instances) given per-row; S=100 in the dataset.
//
// Plan:
//   k0: zero global scratch accumulators
//   k1: per-(seg,group) sums of x and x^2 via per-warp-private shared tables
//       (lane g owns group g => conflict-free non-atomic LDS/STS RMW),
//       block-reduced + global atomicAdd
//   k2: tiny kernel: (mean, inv_std) per (seg, group)
//   k3: normalize: out = (x - mean) * inv * gamma + beta

#define C_     64
#define G_     32
#define S_MAX  1024     // global scratch capacity (dataset S = 100)
#define S_SH   128      // shared-privatized capacity per warp
#define EPS_   1e-5f

__device__ float2 g_s12[S_MAX * G_];   // (sum, sumsq) per (seg, group)
__device__ float  g_cnt[S_MAX];        // rows per seg
__device__ float2 g_stat[S_MAX * G_];  // (mean, inv_std) per (seg, group)

// ---------------- k0: zero scratch ----------------
__global__ void zero_kernel() {
    int i = blockIdx.x * blockDim.x + threadIdx.x;
    if (i < S_MAX * G_) g_s12[i] = make_float2(0.f, 0.f);
    if (i < S_MAX)      g_cnt[i] = 0.f;
}

// ---------------- k1: segmented sums ----------------
#define W1 3     // warps per block
#define U1 16    // row unroll per warp

extern __shared__ unsigned char smem_raw[];

__global__ void __launch_bounds__(W1 * 32, 2)
pass1_kernel(const float2* __restrict__ x2, const int* __restrict__ seg, int N) {
    float2* sh      = (float2*)smem_raw;                    // W1 copies of [S_SH*G_]
    float*  cnt_all = (float*)(sh + W1 * S_SH * G_);        // W1 copies of [S_SH]

    const int warp = threadIdx.x >> 5;
    const int lane = threadIdx.x & 31;

    for (int i = threadIdx.x; i < W1 * S_SH * G_; i += W1 * 32)
        sh[i] = make_float2(0.f, 0.f);
    for (int i = threadIdx.x; i < W1 * S_SH; i += W1 * 32)
        cnt_all[i] = 0.f;
    __syncthreads();

    float2* acc = sh + warp * (S_SH * G_);
    float*  cnt = cnt_all + warp * S_SH;

    const int nw = gridDim.x * W1;
    const int gw = blockIdx.x * W1 + warp;

    int r = gw;
    const int limit = N - (U1 - 1) * nw;   // all U1 rows valid below this
    for (; r < limit; r += nw * U1) {
        int    sg[U1];
        float2 v[U1];
#pragma unroll
        for (int j = 0; j < U1; j++) {
            int row = r + j * nw;
            sg[j] = __ldg(seg + row);
            v[j]  = __ldg(x2 + row * G_ + lane);   // lane g: channels 2g, 2g+1
        }
#pragma unroll
        for (int j = 0; j < U1; j++) {
            float s1 = v[j].x + v[j].y;
            float s2 = fmaf(v[j].x, v[j].x, v[j].y * v[j].y);
            int   s  = sg[j];
            if ((unsigned)s < S_SH) {
                float2 a = acc[s * G_ + lane];
                a.x += s1; a.y += s2;
                acc[s * G_ + lane] = a;
                if (lane == 0) cnt[s] += 1.f;
            } else if ((unsigned)s < S_MAX) {     // fallback (never hit for S=100)
                atomicAdd(&g_s12[s * G_ + lane].x, s1);
                atomicAdd(&g_s12[s * G_ + lane].y, s2);
                if (lane == 0) atomicAdd(&g_cnt[s], 1.f);
            }
        }
    }
    for (; r < N; r += nw) {
        int    s = __ldg(seg + r);
        float2 v = __ldg(x2 + r * G_ + lane);
        float s1 = v.x + v.y;
        float s2 = fmaf(v.x, v.x, v.y * v.y);
        if ((unsigned)s < S_SH) {
            float2 a = acc[s * G_ + lane];
            a.x += s1; a.y += s2;
            acc[s * G_ + lane] = a;
            if (lane == 0) cnt[s] += 1.f;
        } else if ((unsigned)s < S_MAX) {
            atomicAdd(&g_s12[s * G_ + lane].x, s1);
            atomicAdd(&g_s12[s * G_ + lane].y, s2);
            if (lane == 0) atomicAdd(&g_cnt[s], 1.f);
        }
    }
    __syncthreads();

    // reduce warp copies, push to global
    for (int i = threadIdx.x; i < S_SH * G_; i += W1 * 32) {
        float2 t = sh[i];
#pragma unroll
        for (int w = 1; w < W1; w++) {
            float2 u = sh[w * S_SH * G_ + i];
            t.x += u.x; t.y += u.y;
        }
        if (t.x != 0.f || t.y != 0.f) {
            atomicAdd(&g_s12[i].x, t.x);
            atomicAdd(&g_s12[i].y, t.y);
        }
    }
    for (int i = threadIdx.x; i < S_SH; i += W1 * 32) {
        float c = 0.f;
#pragma unroll
        for (int w = 0; w < W1; w++) c += cnt_all[w * S_SH + i];
        if (c != 0.f) atomicAdd(&g_cnt[i], c);
    }
}

// ---------------- k2: stats ----------------
__global__ void stats_kernel() {
    int i = blockIdx.x * blockDim.x + threadIdx.x;
    if (i >= S_MAX * G_) return;
    int   s    = i >> 5;                         // / G_
    float n    = fmaxf(g_cnt[s] * 2.f, 1.f);     // elements = rows * Cg, guarded
    float2 t   = g_s12[i];
    float mean = t.x / n;
    float var  = t.y / n - mean * mean;
    float inv  = rsqrtf(var + EPS_);
    g_stat[i]  = make_float2(mean, inv);
}

// ---------------- k3: normalize ----------------
#define U3 8

__global__ void __launch_bounds__(256)
pass3_kernel(const float2* __restrict__ x2, const int* __restrict__ seg,
             const float* __restrict__ gamma, const float* __restrict__ beta,
             float2* __restrict__ out2, int N) {
    const int lane = threadIdx.x & 31;
    const float2 gm = __ldg((const float2*)gamma + lane);  // channels 2g, 2g+1
    const float2 bt = __ldg((const float2*)beta  + lane);

    const int nw = (gridDim.x * 256) >> 5;
    const int gw = (blockIdx.x * 256 + threadIdx.x) >> 5;

    int r = gw;
    const int limit = N - (U3 - 1) * nw;
    for (; r < limit; r += nw * U3) {
        int    sg[U3];
        float2 v[U3];
#pragma unroll
        for (int j = 0; j < U3; j++) {
            int row = r + j * nw;
            int s   = __ldg(seg + row);
            sg[j]   = min(max(s, 0), S_MAX - 1);     // clamp like jax gather
            v[j]    = __ldg(x2 + row * G_ + lane);
        }
        float2 st[U3];
#pragma unroll
        for (int j = 0; j < U3; j++)
            st[j] = g_stat[sg[j] * G_ + lane];       // hot 25.6KB table (L1)
#pragma unroll
        for (int j = 0; j < U3; j++) {
            int row = r + j * nw;
            float2 o;
            o.x = fmaf((v[j].x - st[j].x) * st[j].y, gm.x, bt.x);
            o.y = fmaf((v[j].y - st[j].x) * st[j].y, gm.y, bt.y);
            out2[row * G_ + lane] = o;
        }
    }
    for (; r < N; r += nw) {
        int s = __ldg(seg + r);
        s = min(max(s, 0), S_MAX - 1);
        float2 v  = __ldg(x2 + r * G_ + lane);
        float2 st = g_stat[s * G_ + lane];
        float2 o;
        o.x = fmaf((v.x - st.x) * st.y, gm.x, bt.x);
        o.y = fmaf((v.y - st.x) * st.y, gm.y, bt.y);
        out2[r * G_ + lane] = o;
    }
}

// ---------------- launch ----------------
extern "C" void kernel_launch(void* const* d_in, const int* in_sizes, int n_in,
                              void* d_out, int out_size) {
    const float* features = (const float*)d_in[0];
    const float* gamma    = (const float*)d_in[1];
    const float* beta     = (const float*)d_in[2];
    const int*   seg      = (const int*)d_in[3];
    // d_in[4] = num_instances (device scalar) — unused; scratch sized to S_MAX.

    const int N = in_sizes[0] / C_;

    const size_t smem1 = (size_t)W1 * S_SH * G_ * sizeof(float2)
                       + (size_t)W1 * S_SH * sizeof(float);   // ~99.8 KB
    cudaFuncSetAttribute(pass1_kernel,
                         cudaFuncAttributeMaxDynamicSharedMemorySize, (int)smem1);

    zero_kernel<<<(S_MAX * G_ + 255) / 256, 256>>>();
    pass1_kernel<<<296, W1 * 32, smem1>>>((const float2*)features, seg, N);
    stats_kernel<<<(S_MAX * G_ + 255) / 256, 256>>>();
    pass3_kernel<<<1184, 256>>>((const float2*)features, seg, gamma, beta,
                                (float2*)d_out, N);
}

// round 2
// speedup vs baseline: 1.3931x; 1.3931x over previous
#include <cuda_runtime.h>

// Segmented GroupNorm: N rows x C=64 channels, G=32 groups (Cg=2), S=100 instances.
//
//   k0 zero:  clear global scratch
//   kh hist:  per-seg row counts (shared histogram)
//   k1 pass1: per-(seg,group) sum/sumsq; per-warp-private shared tables
//             (lane g owns group g -> conflict-free LDS/STS RMW),
//             software-pipelined loads, contiguous per-warp row chunks
//   k2 stats: (mean, inv_std) per (seg,group)
//   k3 pass3: normalize with float4 loads/stores (warp = 2 rows/step)

#define C_     64
#define G_     32
#define S_MAX  1024
#define S_SH   104      // shared-privatized capacity per warp (dataset S=100)
#define EPS_   1e-5f

__device__ float2 g_s12[S_MAX * G_];   // (sum, sumsq) per (seg, group)
__device__ float  g_cnt[S_MAX];        // rows per seg
__device__ float2 g_stat[S_MAX * G_];  // (mean, inv_std) per (seg, group)

// ---------------- k0: zero scratch ----------------
__global__ void zero_kernel() {
    int i = blockIdx.x * blockDim.x + threadIdx.x;
    if (i < S_MAX * G_) g_s12[i] = make_float2(0.f, 0.f);
    if (i < S_MAX)      g_cnt[i] = 0.f;
}

// ---------------- kh: per-seg row counts ----------------
__global__ void __launch_bounds__(256)
hist_kernel(const int* __restrict__ seg, int N) {
    __shared__ int h[S_MAX];
    for (int i = threadIdx.x; i < S_MAX; i += 256) h[i] = 0;
    __syncthreads();
    const int tid = blockIdx.x * 256 + threadIdx.x;
    const int nt  = gridDim.x * 256;
    const int N4  = N >> 2;
    const int4* s4 = (const int4*)seg;
    for (int i = tid; i < N4; i += nt) {
        int4 v = __ldg(s4 + i);
        if ((unsigned)v.x < S_MAX) atomicAdd(&h[v.x], 1);
        if ((unsigned)v.y < S_MAX) atomicAdd(&h[v.y], 1);
        if ((unsigned)v.z < S_MAX) atomicAdd(&h[v.z], 1);
        if ((unsigned)v.w < S_MAX) atomicAdd(&h[v.w], 1);
    }
    for (int i = (N4 << 2) + tid; i < N; i += nt) {
        int v = __ldg(seg + i);
        if ((unsigned)v < S_MAX) atomicAdd(&h[v], 1);
    }
    __syncthreads();
    for (int i = threadIdx.x; i < S_MAX; i += 256)
        if (h[i]) atomicAdd(&g_cnt[i], (float)h[i]);
}

// ---------------- k1: segmented sums (pipelined) ----------------
#define W1 4     // warps per block
#define U1 12    // rows per batch per warp

extern __shared__ float2 sh1[];      // W1 copies of [S_SH*G_]

__device__ __forceinline__ void rmw_row(float2* acc, int lane, int s, float2 v) {
    float s1 = v.x + v.y;
    float s2 = fmaf(v.x, v.x, v.y * v.y);
    if ((unsigned)s < S_SH) {
        float2 a = acc[s * G_ + lane];
        a.x += s1; a.y += s2;
        acc[s * G_ + lane] = a;
    } else if ((unsigned)s < S_MAX) {          // fallback (never hit for S=100)
        atomicAdd(&g_s12[s * G_ + lane].x, s1);
        atomicAdd(&g_s12[s * G_ + lane].y, s2);
    }
}

__global__ void __launch_bounds__(W1 * 32, 2)
pass1_kernel(const float2* __restrict__ x2, const int* __restrict__ seg, int N) {
    const int warp = threadIdx.x >> 5;
    const int lane = threadIdx.x & 31;

    for (int i = threadIdx.x; i < W1 * S_SH * G_; i += W1 * 32)
        sh1[i] = make_float2(0.f, 0.f);
    __syncthreads();
    float2* acc = sh1 + warp * (S_SH * G_);

    // contiguous per-warp row chunk
    const int nwarps = gridDim.x * W1;
    const int gw     = blockIdx.x * W1 + warp;
    const int L      = (N + nwarps - 1) / nwarps;
    int rbeg = gw * L; if (rbeg > N) rbeg = N;
    int rend = rbeg + L; if (rend > N) rend = N;

    int base = rbeg;
    const int fit = rend - U1;       // last start with a full batch
    if (base <= fit) {
        int sgA[U1]; float2 vA[U1];
#pragma unroll
        for (int j = 0; j < U1; j++) {
            int row = base + j;
            sgA[j] = __ldg(seg + row);
            vA[j]  = __ldcs(x2 + (size_t)row * G_ + lane);
        }
        while (true) {
            int  nxt = base + U1;
            bool nv  = nxt <= fit;
            int sgB[U1]; float2 vB[U1];
            if (nv) {
#pragma unroll
                for (int j = 0; j < U1; j++) {
                    int row = nxt + j;
                    sgB[j] = __ldg(seg + row);
                    vB[j]  = __ldcs(x2 + (size_t)row * G_ + lane);
                }
            }
#pragma unroll
            for (int j = 0; j < U1; j++) rmw_row(acc, lane, sgA[j], vA[j]);
            base = nxt;
            if (!nv) break;
#pragma unroll
            for (int j = 0; j < U1; j++) { sgA[j] = sgB[j]; vA[j] = vB[j]; }
        }
    }
    for (int r = base; r < rend; r++) {
        int    s = __ldg(seg + r);
        float2 v = __ldcs(x2 + (size_t)r * G_ + lane);
        rmw_row(acc, lane, s, v);
    }
    __syncthreads();

    // reduce warp copies, push to global
    for (int i = threadIdx.x; i < S_SH * G_; i += W1 * 32) {
        float2 t = sh1[i];
#pragma unroll
        for (int w = 1; w < W1; w++) {
            float2 u = sh1[w * S_SH * G_ + i];
            t.x += u.x; t.y += u.y;
        }
        if (t.x != 0.f || t.y != 0.f) {
            atomicAdd(&g_s12[i].x, t.x);
            atomicAdd(&g_s12[i].y, t.y);
        }
    }
}

// ---------------- k2: stats ----------------
__global__ void stats_kernel() {
    int i = blockIdx.x * blockDim.x + threadIdx.x;
    if (i >= S_MAX * G_) return;
    int   s    = i >> 5;                         // / G_
    float n    = fmaxf(g_cnt[s] * 2.f, 1.f);     // elements = rows * Cg, guarded
    float2 t   = g_s12[i];
    float mean = t.x / n;
    float var  = t.y / n - mean * mean;
    float inv  = rsqrtf(var + EPS_);
    g_stat[i]  = make_float2(mean, inv);
}

// ---------------- k3: normalize (float4, warp = 2 rows/step) ----------------
#define U3 4

__global__ void __launch_bounds__(256)
pass3_kernel(const float4* __restrict__ x4, const int* __restrict__ seg,
             const float* __restrict__ gamma, const float* __restrict__ beta,
             float4* __restrict__ out4, int N) {
    const int lane = threadIdx.x & 31;
    const int q    = lane & 15;       // float4 slot within row: channels 4q..4q+3
    const int h    = lane >> 4;       // row parity within pair

    const float4 gm = __ldg((const float4*)gamma + q);
    const float4 bt = __ldg((const float4*)beta  + q);
    const float4* stat4 = (const float4*)g_stat;   // [s*16+q] = (m2q,i2q,m2q1,i2q1)

    const int P      = N >> 1;                     // row pairs
    const int nwarps = (gridDim.x * 256) >> 5;
    const int gw     = (blockIdx.x * 256 + threadIdx.x) >> 5;
    const int L      = (P + nwarps - 1) / nwarps;  // contiguous pair chunk
    int pbeg = gw * L; if (pbeg > P) pbeg = P;
    int pend = pbeg + L; if (pend > P) pend = P;

    int p = pbeg;
    for (; p + U3 <= pend; p += U3) {
        int sg[U3]; float4 v[U3];
#pragma unroll
        for (int j = 0; j < U3; j++) {
            int row = 2 * (p + j) + h;
            int s   = __ldg(seg + row);
            sg[j]   = min(max(s, 0), S_MAX - 1);
            v[j]    = __ldcs(x4 + (size_t)row * 16 + q);
        }
        float4 st[U3];
#pragma unroll
        for (int j = 0; j < U3; j++)
            st[j] = __ldg(stat4 + sg[j] * 16 + q);
#pragma unroll
        for (int j = 0; j < U3; j++) {
            int row = 2 * (p + j) + h;
            float4 o;
            o.x = fmaf((v[j].x - st[j].x) * st[j].y, gm.x, bt.x);
            o.y = fmaf((v[j].y - st[j].x) * st[j].y, gm.y, bt.y);
            o.z = fmaf((v[j].z - st[j].z) * st[j].w, gm.z, bt.z);
            o.w = fmaf((v[j].w - st[j].z) * st[j].w, gm.w, bt.w);
            __stcs(out4 + (size_t)row * 16 + q, o);
        }
    }
    for (; p < pend; p++) {
        int row = 2 * p + h;
        int s   = min(max(__ldg(seg + row), 0), S_MAX - 1);
        float4 v  = __ldcs(x4 + (size_t)row * 16 + q);
        float4 st = __ldg(stat4 + s * 16 + q);
        float4 o;
        o.x = fmaf((v.x - st.x) * st.y, gm.x, bt.x);
        o.y = fmaf((v.y - st.x) * st.y, gm.y, bt.y);
        o.z = fmaf((v.z - st.z) * st.w, gm.z, bt.z);
        o.w = fmaf((v.w - st.z) * st.w, gm.w, bt.w);
        __stcs(out4 + (size_t)row * 16 + q, o);
    }
    // odd-N tail: one row, handled by global warp 0 with float2 lanes
    if ((N & 1) && gw == 0) {
        int row = N - 1;
        int s   = min(max(__ldg(seg + row), 0), S_MAX - 1);
        const float2* x2 = (const float2*)x4;
        float2 v  = __ldg(x2 + (size_t)row * 32 + lane);
        float2 st = g_stat[s * 32 + lane];
        const float2 gm2 = __ldg((const float2*)gamma + lane);
        const float2 bt2 = __ldg((const float2*)beta  + lane);
        float2 o;
        o.x = fmaf((v.x - st.x) * st.y, gm2.x, bt2.x);
        o.y = fmaf((v.y - st.x) * st.y, gm2.y, bt2.y);
        ((float2*)out4)[(size_t)row * 32 + lane] = o;
    }
}

// ---------------- launch ----------------
extern "C" void kernel_launch(void* const* d_in, const int* in_sizes, int n_in,
                              void* d_out, int out_size) {
    const float* features = (const float*)d_in[0];
    const float* gamma    = (const float*)d_in[1];
    const float* beta     = (const float*)d_in[2];
    const int*   seg      = (const int*)d_in[3];
    // d_in[4] = num_instances (device scalar) — unused; scratch sized to S_MAX.

    const int N = in_sizes[0] / C_;

    const size_t smem1 = (size_t)W1 * S_SH * G_ * sizeof(float2);  // 106496 B
    cudaFuncSetAttribute(pass1_kernel,
                         cudaFuncAttributeMaxDynamicSharedMemorySize, (int)smem1);

    zero_kernel<<<(S_MAX * G_ + 255) / 256, 256>>>();
    hist_kernel<<<296, 256>>>(seg, N);
    pass1_kernel<<<296, W1 * 32, smem1>>>((const float2*)features, seg, N);
    stats_kernel<<<(S_MAX * G_ + 255) / 256, 256>>>();
    pass3_kernel<<<1184, 256>>>((const float4*)features, seg, gamma, beta,
                                (float4*)d_out, N);
}